// round 1
// baseline (speedup 1.0000x reference)
#include <cuda_runtime.h>

#define IMG_H 4096
#define IMG_W 4096
#define NPIX (IMG_H * IMG_W)
#define NITER 5

// Scratch ping-pong buffers for the pred recurrence (static device memory —
// no runtime allocation).
__device__ float g_predA[NPIX];
__device__ float g_predB[NPIX];
// [0] = gt_sum, [1..5] = S_i (sum of false_negative per iteration)
__device__ float g_sums[8];

__global__ void zero_sums_kernel() {
    if (threadIdx.x < 8) g_sums[threadIdx.x] = 0.0f;
}

__device__ __forceinline__ float sigmoid_f(float x) {
    return 1.0f / (1.0f + __expf(-x));
}

// One iteration: dilated = clip(3x3 box sum of pred, 0, 1)
//                sharp   = sigmoid(20*(dilated - pred - 0.5))
//                fn      = gt * sharp
//                pred'   = pred + fn     (skipped on last iteration)
//                S_i    += sum(fn)       (block-reduce + atomic)
// On iteration 0, also accumulate gt_sum.
template <bool WRITE_OUT, bool DO_GT_SUM>
__global__ void iter_kernel(const float* __restrict__ pin,
                            const float* __restrict__ gt,
                            float* __restrict__ pout,
                            int sum_idx) {
    const int x = blockIdx.x * blockDim.x + threadIdx.x;   // blockDim.x == 32
    const int y = blockIdx.y * blockDim.y + threadIdx.y;   // blockDim.y == 8

    float fn = 0.0f;
    float g  = 0.0f;

    if (x < IMG_W && y < IMG_H) {
        const size_t idx = (size_t)y * IMG_W + x;
        float s = 0.0f;
        #pragma unroll
        for (int dy = -1; dy <= 1; ++dy) {
            const int yy = y + dy;
            if (yy < 0 || yy >= IMG_H) continue;
            const float* row = pin + (size_t)yy * IMG_W;
            s += row[x];
            if (x - 1 >= 0)    s += row[x - 1];
            if (x + 1 < IMG_W) s += row[x + 1];
        }
        const float p = pin[idx];
        const float d = fminf(fmaxf(s, 0.0f), 1.0f);
        g = gt[idx];
        const float sharp = sigmoid_f(20.0f * (d - p - 0.5f));
        fn = g * sharp;
        if (WRITE_OUT) pout[idx] = p + fn;
    }

    // Block reduction (256 threads = 8 warps), one atomic per block per sum.
    #pragma unroll
    for (int o = 16; o > 0; o >>= 1)
        fn += __shfl_down_sync(0xffffffffu, fn, o);
    if (DO_GT_SUM) {
        #pragma unroll
        for (int o = 16; o > 0; o >>= 1)
            g += __shfl_down_sync(0xffffffffu, g, o);
    }

    __shared__ float wsum_fn[8];
    __shared__ float wsum_g[8];
    const int lane = threadIdx.x;
    const int wid  = threadIdx.y;
    if (lane == 0) {
        wsum_fn[wid] = fn;
        if (DO_GT_SUM) wsum_g[wid] = g;
    }
    __syncthreads();
    if (wid == 0) {
        float v = (lane < 8) ? wsum_fn[lane] : 0.0f;
        #pragma unroll
        for (int o = 4; o > 0; o >>= 1)
            v += __shfl_down_sync(0xffffffffu, v, o);
        if (lane == 0) atomicAdd(&g_sums[sum_idx], v);

        if (DO_GT_SUM) {
            float vg = (lane < 8) ? wsum_g[lane] : 0.0f;
            #pragma unroll
            for (int o = 4; o > 0; o >>= 1)
                vg += __shfl_down_sync(0xffffffffu, vg, o);
            if (lane == 0) atomicAdd(&g_sums[0], vg);
        }
    }
}

__global__ void finalize_kernel(float* __restrict__ out) {
    const float w[NITER] = {1.0f, 4.0f, 9.0f, 16.0f, 25.0f};
    float t = 0.0f;
    #pragma unroll
    for (int i = 0; i < NITER; ++i) t += w[i] * g_sums[1 + i];
    out[0] = t / g_sums[0];
}

extern "C" void kernel_launch(void* const* d_in, const int* in_sizes, int n_in,
                              void* d_out, int out_size) {
    (void)in_sizes; (void)n_in; (void)out_size;
    const float* pred = (const float*)d_in[0];
    const float* gt   = (const float*)d_in[1];
    float* out        = (float*)d_out;

    float* bufA = nullptr;
    float* bufB = nullptr;
    cudaGetSymbolAddress((void**)&bufA, g_predA);
    cudaGetSymbolAddress((void**)&bufB, g_predB);

    dim3 block(32, 8);
    dim3 grid(IMG_W / 32, IMG_H / 8);

    zero_sums_kernel<<<1, 32>>>();

    // iter 0: input prediction -> A (also computes gt_sum)
    iter_kernel<true,  true ><<<grid, block>>>(pred, gt, bufA, 1);
    // iter 1: A -> B
    iter_kernel<true,  false><<<grid, block>>>(bufA, gt, bufB, 2);
    // iter 2: B -> A
    iter_kernel<true,  false><<<grid, block>>>(bufB, gt, bufA, 3);
    // iter 3: A -> B
    iter_kernel<true,  false><<<grid, block>>>(bufA, gt, bufB, 4);
    // iter 4: B -> (no write, sum only)
    iter_kernel<false, false><<<grid, block>>>(bufB, gt, nullptr, 5);

    finalize_kernel<<<1, 1>>>(out);
}

// round 2
// speedup vs baseline: 4.0650x; 4.0650x over previous
#include <cuda_runtime.h>

#define IMG_H 4096
#define IMG_W 4096
#define NPIX (IMG_H * IMG_W)
#define NITER 5

// Ping-pong scratch (static device memory — no runtime allocation).
__device__ float g_predA[NPIX];
__device__ float g_predB[NPIX];
// [0] = gt_sum, [1..5] = S_i
__device__ float g_sums[8];

__global__ void zero_sums_kernel() {
    if (threadIdx.x < 8) g_sums[threadIdx.x] = 0.0f;
}

// Horizontal 3-tap sums for 4 consecutive outputs from 6 inputs (l, c.xyzw, r)
__device__ __forceinline__ float4 hsum3(float l, float4 c, float r) {
    float4 h;
    h.x = l   + c.x + c.y;
    h.y = c.x + c.y + c.z;
    h.z = c.y + c.z + c.w;
    h.w = c.z + c.w + r;
    return h;
}

// One iteration, 4 pixels per thread (float4).
// blockDim = (64, 4) -> 256 threads, tile 256x4 pixels.
template <bool WRITE_OUT, bool DO_GT_SUM>
__global__ void __launch_bounds__(256)
iter4_kernel(const float* __restrict__ pin,
             const float* __restrict__ gt,
             float* __restrict__ pout,
             int sum_idx) {
    const int tx = blockIdx.x * blockDim.x + threadIdx.x;   // 0..1023
    const int y  = blockIdx.y * blockDim.y + threadIdx.y;   // 0..4095
    const int x0 = tx << 2;                                  // 16B-aligned
    const size_t idx = (size_t)y * IMG_W + x0;

    const bool has_l = (x0 > 0);
    const bool has_r = (x0 + 4 < IMG_W);

    // center row
    const float4 c  = *(const float4*)(pin + idx);
    float cl = has_l ? __ldg(pin + idx - 1) : 0.0f;
    float cr = has_r ? __ldg(pin + idx + 4) : 0.0f;
    float4 hc = hsum3(cl, c, cr);

    // row above
    float4 hu = make_float4(0.f, 0.f, 0.f, 0.f);
    if (y > 0) {
        const size_t iu = idx - IMG_W;
        const float4 u  = *(const float4*)(pin + iu);
        float ul = has_l ? __ldg(pin + iu - 1) : 0.0f;
        float ur = has_r ? __ldg(pin + iu + 4) : 0.0f;
        hu = hsum3(ul, u, ur);
    }

    // row below
    float4 hd = make_float4(0.f, 0.f, 0.f, 0.f);
    if (y < IMG_H - 1) {
        const size_t id = idx + IMG_W;
        const float4 d4 = *(const float4*)(pin + id);
        float dl = has_l ? __ldg(pin + id - 1) : 0.0f;
        float dr = has_r ? __ldg(pin + id + 4) : 0.0f;
        hd = hsum3(dl, d4, dr);
    }

    const float4 g4 = *(const float4*)(gt + idx);

    float4 fn4, po4;
    {
        float s, d, z, sharp;
        // x
        s = hu.x + hc.x + hd.x;
        d = fminf(fmaxf(s, 0.0f), 1.0f);
        z = 20.0f * (d - c.x - 0.5f);
        sharp = __fdividef(1.0f, 1.0f + __expf(-z));
        fn4.x = g4.x * sharp;  po4.x = c.x + fn4.x;
        // y
        s = hu.y + hc.y + hd.y;
        d = fminf(fmaxf(s, 0.0f), 1.0f);
        z = 20.0f * (d - c.y - 0.5f);
        sharp = __fdividef(1.0f, 1.0f + __expf(-z));
        fn4.y = g4.y * sharp;  po4.y = c.y + fn4.y;
        // z
        s = hu.z + hc.z + hd.z;
        d = fminf(fmaxf(s, 0.0f), 1.0f);
        z = 20.0f * (d - c.z - 0.5f);
        sharp = __fdividef(1.0f, 1.0f + __expf(-z));
        fn4.z = g4.z * sharp;  po4.z = c.z + fn4.z;
        // w
        s = hu.w + hc.w + hd.w;
        d = fminf(fmaxf(s, 0.0f), 1.0f);
        z = 20.0f * (d - c.w - 0.5f);
        sharp = __fdividef(1.0f, 1.0f + __expf(-z));
        fn4.w = g4.w * sharp;  po4.w = c.w + fn4.w;
    }

    if (WRITE_OUT) *(float4*)(pout + idx) = po4;

    float fn = (fn4.x + fn4.y) + (fn4.z + fn4.w);
    float gg = 0.0f;
    if (DO_GT_SUM) gg = (g4.x + g4.y) + (g4.z + g4.w);

    // Block reduction (256 threads = 8 warps), one atomic per block per sum.
    #pragma unroll
    for (int o = 16; o > 0; o >>= 1)
        fn += __shfl_down_sync(0xffffffffu, fn, o);
    if (DO_GT_SUM) {
        #pragma unroll
        for (int o = 16; o > 0; o >>= 1)
            gg += __shfl_down_sync(0xffffffffu, gg, o);
    }

    __shared__ float wsum_fn[8];
    __shared__ float wsum_g[8];
    const int tid  = threadIdx.y * blockDim.x + threadIdx.x;
    const int lane = tid & 31;
    const int wid  = tid >> 5;
    if (lane == 0) {
        wsum_fn[wid] = fn;
        if (DO_GT_SUM) wsum_g[wid] = gg;
    }
    __syncthreads();
    if (wid == 0) {
        float v = (lane < 8) ? wsum_fn[lane] : 0.0f;
        #pragma unroll
        for (int o = 4; o > 0; o >>= 1)
            v += __shfl_down_sync(0xffffffffu, v, o);
        if (lane == 0) atomicAdd(&g_sums[sum_idx], v);
        if (DO_GT_SUM) {
            float vg = (lane < 8) ? wsum_g[lane] : 0.0f;
            #pragma unroll
            for (int o = 4; o > 0; o >>= 1)
                vg += __shfl_down_sync(0xffffffffu, vg, o);
            if (lane == 0) atomicAdd(&g_sums[0], vg);
        }
    }
}

__global__ void finalize_kernel(float* __restrict__ out) {
    const float w[NITER] = {1.0f, 4.0f, 9.0f, 16.0f, 25.0f};
    float t = 0.0f;
    #pragma unroll
    for (int i = 0; i < NITER; ++i) t += w[i] * g_sums[1 + i];
    out[0] = t / g_sums[0];
}

extern "C" void kernel_launch(void* const* d_in, const int* in_sizes, int n_in,
                              void* d_out, int out_size) {
    (void)in_sizes; (void)n_in; (void)out_size;
    const float* pred = (const float*)d_in[0];
    const float* gt   = (const float*)d_in[1];
    float* out        = (float*)d_out;

    float* bufA = nullptr;
    float* bufB = nullptr;
    cudaGetSymbolAddress((void**)&bufA, g_predA);
    cudaGetSymbolAddress((void**)&bufB, g_predB);

    dim3 block(64, 4);                       // 256 threads, 4 px/thread in x
    dim3 grid(IMG_W / (64 * 4), IMG_H / 4);  // 16 x 1024

    zero_sums_kernel<<<1, 32>>>();

    iter4_kernel<true,  true ><<<grid, block>>>(pred, gt, bufA, 1);
    iter4_kernel<true,  false><<<grid, block>>>(bufA, gt, bufB, 2);
    iter4_kernel<true,  false><<<grid, block>>>(bufB, gt, bufA, 3);
    iter4_kernel<true,  false><<<grid, block>>>(bufA, gt, bufB, 4);
    iter4_kernel<false, false><<<grid, block>>>(bufB, gt, nullptr, 5);

    finalize_kernel<<<1, 1>>>(out);
}

// round 3
// speedup vs baseline: 5.7380x; 1.4116x over previous
#include <cuda_runtime.h>

#define IMG 4096
#define TILE 56            // owned pixels per tile (both dims)
#define RGN 64             // computed region (halo 4)
#define NROWS 66           // smem rows (input halo 5)
#define SSTR 72            // smem row stride in floats (col idx = logical+4)
#define NITER 5

// [0] = gt_sum, [1] = weighted fn sum
__device__ float g_sums[2];

__global__ void zero_sums_kernel() {
    if (threadIdx.x < 2) g_sums[threadIdx.x] = 0.0f;
}

__device__ __forceinline__ float4 hsum3(float l, float4 c, float r) {
    float4 h;
    h.x = l   + c.x + c.y;
    h.y = c.x + c.y + c.z;
    h.z = c.y + c.z + c.w;
    h.w = c.z + c.w + r;
    return h;
}

__device__ __forceinline__ float fast_sig(float z) {
    return __fdividef(1.0f, 1.0f + __expf(-z));
}

__global__ void __launch_bounds__(256)
fused_kernel(const float* __restrict__ pred, const float* __restrict__ gt) {
    __shared__ float sA[NROWS * SSTR];
    __shared__ float sB[NROWS * SSTR];
    __shared__ float red_w[8], red_g[8];

    const int tx  = threadIdx.x;           // 0..15
    const int ty  = threadIdx.y;           // 0..15
    const int tid = ty * 16 + tx;

    const int ox  = blockIdx.x * TILE - 4;  // global col of logical col 0
    const int gy0 = blockIdx.y * TILE - 5;  // global row of smem row 0

    // ---- fill sA with pred over rows 0..65, logical cols -1..64 (zero-pad OOB)
    for (int e = tid; e < NROWS * NROWS; e += 256) {
        const int r = e / NROWS;
        const int c = e - r * NROWS;            // 0..65 -> logical col c-1
        const int gy = gy0 + r;
        const int gx = ox - 1 + c;
        float v = 0.0f;
        if ((unsigned)gy < (unsigned)IMG && (unsigned)gx < (unsigned)IMG)
            v = pred[(size_t)gy * IMG + gx];
        sA[r * SSTR + c + 3] = v;
    }

    // ---- gt for this thread's 4x4 patch (rows 1+4ty..4+4ty, cols 4tx..4tx+3)
    const bool owner = (tx >= 1) && (tx < 15) && (ty >= 1) && (ty < 15);
    const int gx0 = ox + 4 * tx;
    float4 gtv[4];
    float gt_local = 0.0f;
    #pragma unroll
    for (int i = 0; i < 4; ++i) {
        const int gy = gy0 + 1 + 4 * ty + i;
        float4 g = make_float4(0.f, 0.f, 0.f, 0.f);
        if ((unsigned)gy < (unsigned)IMG) {
            if (gx0 >= 0 && gx0 + 3 < IMG) {
                g = *(const float4*)(gt + (size_t)gy * IMG + gx0);
            } else {
                const float* row = gt + (size_t)gy * IMG;
                if ((unsigned)(gx0 + 0) < (unsigned)IMG) g.x = row[gx0 + 0];
                if ((unsigned)(gx0 + 1) < (unsigned)IMG) g.y = row[gx0 + 1];
                if ((unsigned)(gx0 + 2) < (unsigned)IMG) g.z = row[gx0 + 2];
                if ((unsigned)(gx0 + 3) < (unsigned)IMG) g.w = row[gx0 + 3];
            }
        }
        gtv[i] = g;
        gt_local += (g.x + g.y) + (g.z + g.w);
    }
    if (!owner) gt_local = 0.0f;

    __syncthreads();

    float* cur = sA;
    float* nxt = sB;
    const float wts[NITER] = {1.0f, 4.0f, 9.0f, 16.0f, 25.0f};
    float wacc = 0.0f;

    const int base = (4 * ty) * SSTR + 4 + 4 * tx;   // smem idx of (row 4ty, logical col 4tx)

    #pragma unroll
    for (int k = 1; k <= NITER; ++k) {
        // load 6 rows: smem rows 4ty..4ty+5, cols logical 4tx-1..4tx+4
        float4 c6[6];
        float  l6[6], r6[6];
        #pragma unroll
        for (int r = 0; r < 6; ++r) {
            const float* p = cur + base + r * SSTR;
            c6[r] = *(const float4*)p;
            l6[r] = p[-1];
            r6[r] = p[4];
        }
        float4 hs[6];
        #pragma unroll
        for (int r = 0; r < 6; ++r) hs[r] = hsum3(l6[r], c6[r], r6[r]);

        float fn_iter = 0.0f;
        #pragma unroll
        for (int i = 0; i < 4; ++i) {
            float4 box;
            box.x = hs[i].x + hs[i + 1].x + hs[i + 2].x;
            box.y = hs[i].y + hs[i + 1].y + hs[i + 2].y;
            box.z = hs[i].z + hs[i + 1].z + hs[i + 2].z;
            box.w = hs[i].w + hs[i + 1].w + hs[i + 2].w;
            const float4 p = c6[i + 1];
            const float4 g = gtv[i];

            float4 fn4, pn4;
            {
                float d, z;
                d = fminf(fmaxf(box.x, 0.0f), 1.0f);
                z = 20.0f * (d - p.x - 0.5f);
                fn4.x = g.x * fast_sig(z); pn4.x = p.x + fn4.x;
                d = fminf(fmaxf(box.y, 0.0f), 1.0f);
                z = 20.0f * (d - p.y - 0.5f);
                fn4.y = g.y * fast_sig(z); pn4.y = p.y + fn4.y;
                d = fminf(fmaxf(box.z, 0.0f), 1.0f);
                z = 20.0f * (d - p.z - 0.5f);
                fn4.z = g.z * fast_sig(z); pn4.z = p.z + fn4.z;
                d = fminf(fmaxf(box.w, 0.0f), 1.0f);
                z = 20.0f * (d - p.w - 0.5f);
                fn4.w = g.w * fast_sig(z); pn4.w = p.w + fn4.w;
            }
            fn_iter += (fn4.x + fn4.y) + (fn4.z + fn4.w);

            if (k < NITER) {
                const int pr = 1 + 4 * ty + i;               // output smem row
                const bool row_ok = (pr >= k) && (pr <= 65 - k);
                if (row_ok) {
                    const int pc0 = 4 * tx;                  // logical col
                    const bool col_full = (pc0 >= k - 1) && (pc0 + 3 <= 64 - k);
                    float* dst = nxt + pr * SSTR + 4 + pc0;
                    if (col_full) {
                        *(float4*)dst = pn4;
                    } else {
                        if (pc0 + 0 >= k - 1 && pc0 + 0 <= 64 - k) dst[0] = pn4.x;
                        if (pc0 + 1 >= k - 1 && pc0 + 1 <= 64 - k) dst[1] = pn4.y;
                        if (pc0 + 2 >= k - 1 && pc0 + 2 <= 64 - k) dst[2] = pn4.z;
                        if (pc0 + 3 >= k - 1 && pc0 + 3 <= 64 - k) dst[3] = pn4.w;
                    }
                }
            }
        }
        if (owner) wacc += wts[k - 1] * fn_iter;

        if (k < NITER) {
            __syncthreads();
            float* t = cur; cur = nxt; nxt = t;
        }
    }

    // ---- block reduction: wacc and gt_local, one atomic each per block
    #pragma unroll
    for (int o = 16; o > 0; o >>= 1) {
        wacc     += __shfl_down_sync(0xffffffffu, wacc, o);
        gt_local += __shfl_down_sync(0xffffffffu, gt_local, o);
    }
    const int lane = tid & 31;
    const int wid  = tid >> 5;
    if (lane == 0) { red_w[wid] = wacc; red_g[wid] = gt_local; }
    __syncthreads();
    if (wid == 0) {
        float v = (lane < 8) ? red_w[lane] : 0.0f;
        float g = (lane < 8) ? red_g[lane] : 0.0f;
        #pragma unroll
        for (int o = 4; o > 0; o >>= 1) {
            v += __shfl_down_sync(0xffffffffu, v, o);
            g += __shfl_down_sync(0xffffffffu, g, o);
        }
        if (lane == 0) {
            atomicAdd(&g_sums[1], v);
            atomicAdd(&g_sums[0], g);
        }
    }
}

__global__ void finalize_kernel(float* __restrict__ out) {
    out[0] = g_sums[1] / g_sums[0];
}

extern "C" void kernel_launch(void* const* d_in, const int* in_sizes, int n_in,
                              void* d_out, int out_size) {
    (void)in_sizes; (void)n_in; (void)out_size;
    const float* pred = (const float*)d_in[0];
    const float* gt   = (const float*)d_in[1];
    float* out        = (float*)d_out;

    const int ntiles = (IMG + TILE - 1) / TILE;   // 74
    dim3 block(16, 16);
    dim3 grid(ntiles, ntiles);

    zero_sums_kernel<<<1, 32>>>();
    fused_kernel<<<grid, block>>>(pred, gt);
    finalize_kernel<<<1, 1>>>(out);
}

// round 4
// speedup vs baseline: 6.2530x; 1.0897x over previous
#include <cuda_runtime.h>

#define IMG 4096
#define TILE 56            // owned pixels per tile (both dims)
#define NROWS 66           // smem rows (input halo 5)
#define SSTR 72            // smem row stride in floats
#define NITER 5

// [0] = gt_sum, [1] = weighted fn sum  (self-resetting: finalize zeroes them)
__device__ float g_sums[2];

__device__ __forceinline__ float4 hsum3(float l, float4 c, float r) {
    float4 h;
    h.x = l   + c.x + c.y;
    h.y = c.x + c.y + c.z;
    h.z = c.y + c.z + c.w;
    h.w = c.z + c.w + r;
    return h;
}

__device__ __forceinline__ float tanh_fast(float x) {
    float r;
    asm("tanh.approx.f32 %0, %1;" : "=f"(r) : "f"(x));
    return r;
}

__global__ void __launch_bounds__(256)
fused_kernel(const float* __restrict__ pred, const float* __restrict__ gt) {
    __shared__ float sA[NROWS * SSTR];
    __shared__ float sB[NROWS * SSTR];
    __shared__ float red_w[8], red_g[8];

    const int tx  = threadIdx.x;           // 0..15
    const int ty  = threadIdx.y;           // 0..15
    const int tid = ty * 16 + tx;

    const int ox  = blockIdx.x * TILE - 4;  // global col of logical col 0
    const int gy0 = blockIdx.y * TILE - 5;  // global row of smem row 0

    // ---- fill sA with pred over rows 0..65, logical cols -1..64 (zero-pad OOB)
    for (int e = tid; e < NROWS * NROWS; e += 256) {
        const int r = e / NROWS;
        const int c = e - r * NROWS;            // 0..65 -> logical col c-1
        const int gy = gy0 + r;
        const int gx = ox - 1 + c;
        float v = 0.0f;
        if ((unsigned)gy < (unsigned)IMG && (unsigned)gx < (unsigned)IMG)
            v = pred[(size_t)gy * IMG + gx];
        sA[r * SSTR + c + 3] = v;
    }

    // ---- gt for this thread's 4x4 patch
    const bool owner = (tx >= 1) && (tx < 15) && (ty >= 1) && (ty < 15);
    const int gx0 = ox + 4 * tx;
    float4 gtv[4];
    float gt_local = 0.0f;
    #pragma unroll
    for (int i = 0; i < 4; ++i) {
        const int gy = gy0 + 1 + 4 * ty + i;
        float4 g = make_float4(0.f, 0.f, 0.f, 0.f);
        if ((unsigned)gy < (unsigned)IMG) {
            if (gx0 >= 0 && gx0 + 3 < IMG) {
                g = *(const float4*)(gt + (size_t)gy * IMG + gx0);
            } else {
                const float* row = gt + (size_t)gy * IMG;
                if ((unsigned)(gx0 + 0) < (unsigned)IMG) g.x = row[gx0 + 0];
                if ((unsigned)(gx0 + 1) < (unsigned)IMG) g.y = row[gx0 + 1];
                if ((unsigned)(gx0 + 2) < (unsigned)IMG) g.z = row[gx0 + 2];
                if ((unsigned)(gx0 + 3) < (unsigned)IMG) g.w = row[gx0 + 3];
            }
        }
        gtv[i] = g;
        gt_local += (g.x + g.y) + (g.z + g.w);
    }
    if (!owner) gt_local = 0.0f;

    __syncthreads();

    float* cur = sA;
    float* nxt = sB;
    const float wts[NITER] = {1.0f, 4.0f, 9.0f, 16.0f, 25.0f};
    float wacc = 0.0f;

    const int base = (4 * ty) * SSTR + 4 + 4 * tx;
    const bool is_l = (tx == 0);
    const bool is_r = (tx == 15);

    #pragma unroll
    for (int k = 1; k <= NITER; ++k) {
        // load 6 rows: center float4 via LDS.128; neighbors via warp shuffle
        float4 c6[6];
        float  l6[6], r6[6];
        #pragma unroll
        for (int r = 0; r < 6; ++r) {
            const float* p = cur + base + r * SSTR;
            c6[r] = *(const float4*)p;
            float lw = __shfl_up_sync(0xffffffffu, c6[r].w, 1);
            float rx = __shfl_down_sync(0xffffffffu, c6[r].x, 1);
            l6[r] = is_l ? p[-1] : lw;
            r6[r] = is_r ? p[4]  : rx;
        }
        float4 hs[6];
        #pragma unroll
        for (int r = 0; r < 6; ++r) hs[r] = hsum3(l6[r], c6[r], r6[r]);

        float fn_iter = 0.0f;
        #pragma unroll
        for (int i = 0; i < 4; ++i) {
            float4 box;
            box.x = hs[i].x + hs[i + 1].x + hs[i + 2].x;
            box.y = hs[i].y + hs[i + 1].y + hs[i + 2].y;
            box.z = hs[i].z + hs[i + 1].z + hs[i + 2].z;
            box.w = hs[i].w + hs[i + 1].w + hs[i + 2].w;
            const float4 p = c6[i + 1];
            const float4 g = gtv[i];

            // sharp = sigmoid(20*(d - p - 0.5)) = 0.5*tanh(10*(d-p-0.5)) + 0.5
            float4 fn4, pn4;
            {
                float d, t;
                d = fminf(fmaxf(box.x, 0.0f), 1.0f);
                t = tanh_fast(fmaf(10.0f, d - p.x, -5.0f));
                fn4.x = g.x * fmaf(0.5f, t, 0.5f); pn4.x = p.x + fn4.x;
                d = fminf(fmaxf(box.y, 0.0f), 1.0f);
                t = tanh_fast(fmaf(10.0f, d - p.y, -5.0f));
                fn4.y = g.y * fmaf(0.5f, t, 0.5f); pn4.y = p.y + fn4.y;
                d = fminf(fmaxf(box.z, 0.0f), 1.0f);
                t = tanh_fast(fmaf(10.0f, d - p.z, -5.0f));
                fn4.z = g.z * fmaf(0.5f, t, 0.5f); pn4.z = p.z + fn4.z;
                d = fminf(fmaxf(box.w, 0.0f), 1.0f);
                t = tanh_fast(fmaf(10.0f, d - p.w, -5.0f));
                fn4.w = g.w * fmaf(0.5f, t, 0.5f); pn4.w = p.w + fn4.w;
            }
            fn_iter += (fn4.x + fn4.y) + (fn4.z + fn4.w);

            if (k < NITER) {
                const int pr = 1 + 4 * ty + i;               // output smem row
                const bool row_ok = (pr >= k) && (pr <= 65 - k);
                if (row_ok) {
                    const int pc0 = 4 * tx;                  // logical col
                    const bool col_full = (pc0 >= k - 1) && (pc0 + 3 <= 64 - k);
                    float* dst = nxt + pr * SSTR + 4 + pc0;
                    if (col_full) {
                        *(float4*)dst = pn4;
                    } else {
                        if (pc0 + 0 >= k - 1 && pc0 + 0 <= 64 - k) dst[0] = pn4.x;
                        if (pc0 + 1 >= k - 1 && pc0 + 1 <= 64 - k) dst[1] = pn4.y;
                        if (pc0 + 2 >= k - 1 && pc0 + 2 <= 64 - k) dst[2] = pn4.z;
                        if (pc0 + 3 >= k - 1 && pc0 + 3 <= 64 - k) dst[3] = pn4.w;
                    }
                }
            }
        }
        if (owner) wacc += wts[k - 1] * fn_iter;

        if (k < NITER) {
            __syncthreads();
            float* t = cur; cur = nxt; nxt = t;
        }
    }

    // ---- block reduction, one atomic each per block
    #pragma unroll
    for (int o = 16; o > 0; o >>= 1) {
        wacc     += __shfl_down_sync(0xffffffffu, wacc, o);
        gt_local += __shfl_down_sync(0xffffffffu, gt_local, o);
    }
    const int lane = tid & 31;
    const int wid  = tid >> 5;
    if (lane == 0) { red_w[wid] = wacc; red_g[wid] = gt_local; }
    __syncthreads();
    if (wid == 0) {
        float v = (lane < 8) ? red_w[lane] : 0.0f;
        float g = (lane < 8) ? red_g[lane] : 0.0f;
        #pragma unroll
        for (int o = 4; o > 0; o >>= 1) {
            v += __shfl_down_sync(0xffffffffu, v, o);
            g += __shfl_down_sync(0xffffffffu, g, o);
        }
        if (lane == 0) {
            atomicAdd(&g_sums[1], v);
            atomicAdd(&g_sums[0], g);
        }
    }
}

// Reads accumulators, writes output, then resets them for the next replay.
__global__ void finalize_kernel(float* __restrict__ out) {
    out[0] = g_sums[1] / g_sums[0];
    g_sums[0] = 0.0f;
    g_sums[1] = 0.0f;
}

extern "C" void kernel_launch(void* const* d_in, const int* in_sizes, int n_in,
                              void* d_out, int out_size) {
    (void)in_sizes; (void)n_in; (void)out_size;
    const float* pred = (const float*)d_in[0];
    const float* gt   = (const float*)d_in[1];
    float* out        = (float*)d_out;

    const int ntiles = (IMG + TILE - 1) / TILE;   // 74
    dim3 block(16, 16);
    dim3 grid(ntiles, ntiles);

    fused_kernel<<<grid, block>>>(pred, gt);
    finalize_kernel<<<1, 1>>>(out);
}